// round 10
// baseline (speedup 1.0000x reference)
#include <cuda_runtime.h>
#include <cuda_bf16.h>
#include <mma.h>
#include <cstdint>
#include <cstddef>

using namespace nvcuda;

#define DEPTH 18
#define NNODES ((1 << DEPTH) - 1)      // 262143
#define HDIM 128
#define LEAF_N (1 << (DEPTH - 1))      // 131072

// ================= device scratch (516 MiB total; largest object 192 MiB) =====
__device__ __align__(128) float g_h[(size_t)NNODES * HDIM];          // 128 MiB
__device__ __align__(128) float g_c[(size_t)NNODES * HDIM];          // 128 MiB
__device__ __align__(128) float g_fraw[(size_t)LEAF_N * HDIM];       // 64 MiB: raw fgate pre-act
__device__ __align__(128) float g_iouraw[(size_t)LEAF_N * 384];      // 192 MiB: raw iou pre-act
// weight images, bf16 pairs packed in uint32: [tile][n(128)][kpair(128)] (K=256)
// tiles 0-2: [W_iou;U_iou] n-tiles, tile 3: [W_f;U_f]
__device__ __align__(128) uint32_t g_Bhi[4 * 128 * 128];
__device__ __align__(128) uint32_t g_Blo[4 * 128 * 128];

__device__ __forceinline__ float sigmf(float x) { return 1.0f / (1.0f + __expf(-x)); }

// pure-integer bf16 hi/lo split (truncation): hi = top16(f), lo = top16(f - hi)
__device__ __forceinline__ void split2(float f0, float f1, uint32_t& hiw, uint32_t& low) {
    const uint32_t h0 = __float_as_uint(f0) & 0xFFFF0000u;
    const uint32_t h1 = __float_as_uint(f1) & 0xFFFF0000u;
    const uint32_t l0 = __float_as_uint(f0 - __uint_as_float(h0)) & 0xFFFF0000u;
    const uint32_t l1 = __float_as_uint(f1 - __uint_as_float(h1)) & 0xFFFF0000u;
    hiw = (h0 >> 16) | h1;
    low = (l0 >> 16) | l1;
}

// ================= static smem layout (bf16 elems, 40-elem padded rows) =====
#define PADK 40
#define E_ALO 5120
#define E_BHI 10240
#define E_BLO 15360
#define SM_ELEMS 20480            // 40 KB

// ================= one-time weight prep =================
__global__ void prep_weights(const float* __restrict__ Wiou, const float* __restrict__ Wf,
                             const float* __restrict__ Uiou, const float* __restrict__ Uf)
{
    const int idx = blockIdx.x * blockDim.x + threadIdx.x;
    if (idx >= 4 * 128 * 128) return;
    const int t = idx >> 14;
    const int n = (idx >> 7) & 127;
    const int kp = idx & 127;
    float v[2];
    #pragma unroll
    for (int e = 0; e < 2; e++) {
        const int k = kp * 2 + e;
        if (t < 3) {
            const int nn = t * 128 + n;
            v[e] = (k < 128) ? Wiou[k * 384 + nn] : Uiou[(k - 128) * 384 + nn];
        } else {
            v[e] = (k < 128) ? Wf[k * 128 + n] : Uf[(k - 128) * 128 + n];
        }
    }
    uint32_t hiw, low;
    split2(v[0], v[1], hiw, low);
    g_Bhi[idx] = hiw;
    g_Blo[idx] = low;
}

// ================= wmma GEMM core =================
// CTA = 128 rows x 128 cols, 8 warps (wm 0..3 = 32 rows, wn 0..1 = 64 cols).
// K chunked by 32; chunk kc<4 sources pe (emb row), kc>=4 sources ph0(+ph1 summed).
// bf16-split: acc += A_hi*B_hi + A_hi*B_lo + A_lo*B_hi (fragments register-cached).
__device__ __forceinline__ void gemm_core(
    __nv_bfloat16* sm, int tid,
    const float* pe, const float* ph0, const float* ph1,   // per-thread row ptrs (nullable)
    int nkc,
    const uint32_t* bhi, const uint32_t* blo,              // weight tile base (128n x 128kp)
    float* __restrict__ C, int ldC, int m0, int colbase)
{
    const int wid = tid >> 5;
    const int wm = wid >> 1;
    const int wn = wid & 1;
    const int r = tid >> 1;
    const int sel = tid & 1;

    wmma::fragment<wmma::accumulator, 16, 16, 16, float> acc[2][4];
    #pragma unroll
    for (int mt = 0; mt < 2; mt++)
        #pragma unroll
        for (int nt = 0; nt < 4; nt++)
            wmma::fill_fragment(acc[mt][nt], 0.0f);

    for (int kc = 0; kc < nkc; kc++) {
        __syncthreads();   // protects smem reuse across chunks AND across gemm_core calls
        // ---- stage A chunk (2 threads per row, 16 floats each) ----
        {
            const float* p0;
            const float* p1 = nullptr;
            if (kc < 4) {
                p0 = pe ? pe + kc * 32 + sel * 16 : nullptr;
            } else {
                p0 = ph0 ? ph0 + (kc - 4) * 32 + sel * 16 : nullptr;
                p1 = ph1 ? ph1 + (kc - 4) * 32 + sel * 16 : nullptr;
            }
            uint32_t* dhi = (uint32_t*)(sm + r * PADK) + sel * 8;
            uint32_t* dlo = (uint32_t*)(sm + E_ALO + r * PADK) + sel * 8;
            if (p0) {
                #pragma unroll
                for (int q = 0; q < 4; q++) {
                    float4 f = *(const float4*)(p0 + 4 * q);
                    if (p1) {
                        const float4 g = *(const float4*)(p1 + 4 * q);
                        f.x += g.x; f.y += g.y; f.z += g.z; f.w += g.w;
                    }
                    uint32_t h0, l0, h1, l1;
                    split2(f.x, f.y, h0, l0);
                    split2(f.z, f.w, h1, l1);
                    dhi[2 * q] = h0; dhi[2 * q + 1] = h1;
                    dlo[2 * q] = l0; dlo[2 * q + 1] = l1;
                }
            } else {
                #pragma unroll
                for (int q = 0; q < 8; q++) { dhi[q] = 0u; dlo[q] = 0u; }
            }
        }
        // ---- stage B chunk: 128 n-rows x 32 k (4 uint4/row; row = 32 uint4) ----
        {
            const uint4* shi = (const uint4*)bhi + kc * 4;
            const uint4* slo = (const uint4*)blo + kc * 4;
            #pragma unroll
            for (int i = tid; i < 512; i += 256) {
                const int nn = i >> 2;
                const int q = i & 3;
                *(uint4*)(sm + E_BHI + nn * PADK + q * 8) = shi[nn * 32 + q];
                *(uint4*)(sm + E_BLO + nn * PADK + q * 8) = slo[nn * 32 + q];
            }
        }
        __syncthreads();

        #pragma unroll
        for (int ks = 0; ks < 2; ks++) {
            wmma::fragment<wmma::matrix_a, 16, 16, 16, __nv_bfloat16, wmma::row_major> a_hi[2], a_lo[2];
            #pragma unroll
            for (int mt = 0; mt < 2; mt++) {
                const int arow = (wm * 32 + mt * 16) * PADK + ks * 16;
                wmma::load_matrix_sync(a_hi[mt], sm + arow, PADK);
                wmma::load_matrix_sync(a_lo[mt], sm + E_ALO + arow, PADK);
            }
            #pragma unroll
            for (int nt = 0; nt < 4; nt++) {
                const int brow = (wn * 64 + nt * 16) * PADK + ks * 16;
                wmma::fragment<wmma::matrix_b, 16, 16, 16, __nv_bfloat16, wmma::col_major> b_hi, b_lo;
                wmma::load_matrix_sync(b_hi, sm + E_BHI + brow, PADK);
                wmma::load_matrix_sync(b_lo, sm + E_BLO + brow, PADK);
                #pragma unroll
                for (int mt = 0; mt < 2; mt++) {
                    wmma::mma_sync(acc[mt][nt], a_hi[mt], b_hi, acc[mt][nt]);
                    wmma::mma_sync(acc[mt][nt], a_hi[mt], b_lo, acc[mt][nt]);
                    wmma::mma_sync(acc[mt][nt], a_lo[mt], b_hi, acc[mt][nt]);
                }
            }
        }
    }

    #pragma unroll
    for (int mt = 0; mt < 2; mt++)
        #pragma unroll
        for (int nt = 0; nt < 4; nt++) {
            const int row0 = m0 + wm * 32 + mt * 16;
            const int col0 = colbase + wn * 64 + nt * 16;
            wmma::store_matrix_sync(C + (size_t)row0 * ldC + col0, acc[mt][nt],
                                    ldC, wmma::mem_row_major);
        }
}

// leaves: g_iouraw[m] = emb(leaf m) @ W_iou (K=128); grid (3, 1024)
__global__ __launch_bounds__(256, 2)
void leaf_gemm(const int* __restrict__ xids, const int* __restrict__ msk,
               const float* __restrict__ emb)
{
    __shared__ __align__(16) __nv_bfloat16 sm[SM_ELEMS];
    const int tid = threadIdx.x;
    const int bt = blockIdx.x;
    const int m0 = blockIdx.y * 128;

    const int node = (LEAF_N - 1) + m0 + (tid >> 1);
    const int gid = xids[node] * msk[node];
    const float* pe = emb + (size_t)gid * HDIM;

    gemm_core(sm, tid, pe, nullptr, nullptr, 4,
              g_Bhi + bt * 16384, g_Blo + bt * 16384,
              g_iouraw, 384, m0, bt * 128);
}

// internal level: bx 0..2 = iou n-tiles (A=[emb(node)|h_l+h_r], K=256),
//                 bx 3    = fgate      (A=[emb(parent)|h_child], K=256)
__global__ __launch_bounds__(256, 2)
void level_gemm(const int* __restrict__ xids, const int* __restrict__ msk,
                const float* __restrict__ emb, int s0, int n)
{
    __shared__ __align__(16) __nv_bfloat16 sm[SM_ELEMS];
    const int tid = threadIdx.x;
    const int bx = blockIdx.x;
    const int m0 = blockIdx.y * 128;
    const int s1 = 2 * s0 + 1;
    const int r = tid >> 1;

    const float* pe = nullptr;
    const float* ph0 = nullptr;
    const float* ph1 = nullptr;

    if (bx < 3) {
        if (m0 >= n) return;
        const int m = m0 + r;
        if (m < n) {
            const int node = s0 + m;
            const int gid = xids[node] * msk[node];
            pe  = emb + (size_t)gid * HDIM;
            ph0 = g_h + (size_t)(s1 + 2 * m) * HDIM;
            ph1 = g_h + (size_t)(s1 + 2 * m + 1) * HDIM;
        }
        gemm_core(sm, tid, pe, ph0, ph1, 8,
                  g_Bhi + bx * 16384, g_Blo + bx * 16384,
                  g_iouraw, 384, m0, bx * 128);
    } else {
        const int ch = m0 + r;
        if (ch < 2 * n) {
            const int parent = s0 + (ch >> 1);
            const int gid = xids[parent] * msk[parent];
            pe  = emb + (size_t)gid * HDIM;
            ph0 = g_h + (size_t)(s1 + ch) * HDIM;
        }
        gemm_core(sm, tid, pe, ph0, nullptr, 8,
                  g_Bhi + 3 * 16384, g_Blo + 3 * 16384,
                  g_fraw, 128, m0, 0);
    }
}

// ================= fused tail: levels d=6..0 in ONE CTA =================
__global__ __launch_bounds__(256)
void small_levels(const int* __restrict__ xids, const int* __restrict__ msk,
                  const float* __restrict__ emb,
                  const float* __restrict__ biou, const float* __restrict__ bfv)
{
    __shared__ __align__(16) __nv_bfloat16 sm[SM_ELEMS];
    const int tid = threadIdx.x;
    const int r = tid >> 1;

    for (int d = 6; d >= 0; --d) {
        const int n = 1 << d;
        const int s0 = n - 1;
        const int s1 = 2 * s0 + 1;

        // fgate GEMM: rows = 2n (<=128)
        {
            const float* pe = nullptr;
            const float* ph0 = nullptr;
            if (r < 2 * n) {
                const int parent = s0 + (r >> 1);
                const int gid = xids[parent] * msk[parent];
                pe  = emb + (size_t)gid * HDIM;
                ph0 = g_h + (size_t)(s1 + r) * HDIM;
            }
            gemm_core(sm, tid, pe, ph0, nullptr, 8,
                      g_Bhi + 3 * 16384, g_Blo + 3 * 16384,
                      g_fraw, 128, 0, 0);
        }
        // iou GEMMs: rows = n (<=64), 3 n-tiles
        for (int bt = 0; bt < 3; bt++) {
            const float* pe = nullptr;
            const float* ph0 = nullptr;
            const float* ph1 = nullptr;
            if (r < n) {
                const int node = s0 + r;
                const int gid = xids[node] * msk[node];
                pe  = emb + (size_t)gid * HDIM;
                ph0 = g_h + (size_t)(s1 + 2 * r) * HDIM;
                ph1 = g_h + (size_t)(s1 + 2 * r + 1) * HDIM;
            }
            gemm_core(sm, tid, pe, ph0, ph1, 8,
                      g_Bhi + bt * 16384, g_Blo + bt * 16384,
                      g_iouraw, 384, 0, bt * 128);
        }
        __syncthreads();
        // gate update for this level
        for (int idx = tid; idx < n * HDIM; idx += 256) {
            const int m = idx >> 7;
            const int j = idx & 127;
            const int node = s0 + m;
            const float bf = bfv[j];
            const float c0 = g_c[(size_t)(2 * node + 1) * HDIM + j];
            const float c1 = g_c[(size_t)(2 * node + 2) * HDIM + j];
            const float f0 = sigmf(g_fraw[(size_t)(2 * m) * HDIM + j] + bf);
            const float f1 = sigmf(g_fraw[(size_t)(2 * m + 1) * HDIM + j] + bf);
            const float fc = f0 * c0 + f1 * c1;
            const float iv = g_iouraw[(size_t)m * 384 + j]       + biou[j];
            const float ov = g_iouraw[(size_t)m * 384 + 128 + j] + biou[128 + j];
            const float uv = g_iouraw[(size_t)m * 384 + 256 + j] + biou[256 + j];
            const float cv = sigmf(iv) * tanhf(uv) + fc;
            const float hv = sigmf(ov) * tanhf(cv);
            g_c[(size_t)node * HDIM + j] = cv;
            g_h[(size_t)node * HDIM + j] = hv;
        }
        __syncthreads();
    }
}

// ================= elementwise (biases folded here) =================
__global__ void leaf_update(const float* __restrict__ biou)
{
    const int idx = blockIdx.x * blockDim.x + threadIdx.x;
    if (idx >= LEAF_N * HDIM) return;
    const int m = idx >> 7;
    const int j = idx & 127;
    const int node = (LEAF_N - 1) + m;
    const float iv = g_iouraw[(size_t)m * 384 + j]       + biou[j];
    const float ov = g_iouraw[(size_t)m * 384 + 128 + j] + biou[128 + j];
    const float uv = g_iouraw[(size_t)m * 384 + 256 + j] + biou[256 + j];
    const float cv = sigmf(iv) * tanhf(uv);
    const float hv = sigmf(ov) * tanhf(cv);
    g_c[(size_t)node * HDIM + j] = cv;
    g_h[(size_t)node * HDIM + j] = hv;
}

__global__ void level_update(int s0, int n,
                             const float* __restrict__ biou, const float* __restrict__ bfv)
{
    const int idx = blockIdx.x * blockDim.x + threadIdx.x;
    if (idx >= n * HDIM) return;
    const int m = idx >> 7;
    const int j = idx & 127;
    const int node = s0 + m;
    const float bf = bfv[j];
    const float c0 = g_c[(size_t)(2 * node + 1) * HDIM + j];
    const float c1 = g_c[(size_t)(2 * node + 2) * HDIM + j];
    const float f0 = sigmf(g_fraw[(size_t)(2 * m) * HDIM + j] + bf);
    const float f1 = sigmf(g_fraw[(size_t)(2 * m + 1) * HDIM + j] + bf);
    const float fc = f0 * c0 + f1 * c1;
    const float iv = g_iouraw[(size_t)m * 384 + j]       + biou[j];
    const float ov = g_iouraw[(size_t)m * 384 + 128 + j] + biou[128 + j];
    const float uv = g_iouraw[(size_t)m * 384 + 256 + j] + biou[256 + j];
    const float cv = sigmf(iv) * tanhf(uv) + fc;
    const float hv = sigmf(ov) * tanhf(cv);
    g_c[(size_t)node * HDIM + j] = cv;
    g_h[(size_t)node * HDIM + j] = hv;
}

// ================= output projection =================
__global__ void out_gemm(const float* __restrict__ Wout,
                         const float* __restrict__ bout,
                         float* __restrict__ out)
{
    __shared__ float Ws[HDIM * 5];
    __shared__ float bs[5];
    const int tid = threadIdx.x;
    for (int i = tid; i < HDIM * 5; i += blockDim.x) Ws[i] = Wout[i];
    if (tid < 5) bs[tid] = bout[tid];
    __syncthreads();

    const int node = (blockIdx.x * blockDim.x + tid) >> 5;
    const int lane = tid & 31;
    if (node >= NNODES) return;

    const float* hp = g_h + (size_t)node * HDIM;
    float p[5] = {0.f, 0.f, 0.f, 0.f, 0.f};
    #pragma unroll
    for (int e = 0; e < 4; e++) {
        const int k = e * 32 + lane;
        const float x = hp[k];
        #pragma unroll
        for (int c = 0; c < 5; c++) p[c] += x * Ws[k * 5 + c];
    }
    #pragma unroll
    for (int off = 16; off > 0; off >>= 1)
        #pragma unroll
        for (int c = 0; c < 5; c++)
            p[c] += __shfl_xor_sync(0xffffffffu, p[c], off);

    if (lane == 0) {
        #pragma unroll
        for (int c = 0; c < 5; c++)
            out[(size_t)node * 5 + c] = p[c] + bs[c];
    }
}

// ================= launch =================
extern "C" void kernel_launch(void* const* d_in, const int* in_sizes, int n_in,
                              void* d_out, int out_size)
{
    const int*   x_ids = (const int*)d_in[0];
    const int*   mask  = (const int*)d_in[1];
    const float* emb   = (const float*)d_in[2];
    const float* W_iou = (const float*)d_in[3];
    const float* U_iou = (const float*)d_in[4];
    const float* b_iou = (const float*)d_in[5];
    const float* W_f   = (const float*)d_in[6];
    const float* U_f   = (const float*)d_in[7];
    const float* b_f   = (const float*)d_in[8];
    const float* W_out = (const float*)d_in[9];
    const float* b_out = (const float*)d_in[10];
    float* out = (float*)d_out;

    prep_weights<<<(4 * 128 * 128 + 255) / 256, 256>>>(W_iou, W_f, U_iou, U_f);

    {
        dim3 grid(3, LEAF_N / 128);
        leaf_gemm<<<grid, 256>>>(x_ids, mask, emb);
        leaf_update<<<(LEAF_N * HDIM + 255) / 256, 256>>>(b_iou);
    }

    for (int d = DEPTH - 2; d >= 7; --d) {
        const int n = 1 << d;
        const int s0 = n - 1;
        dim3 grid(4, (2 * n + 127) / 128);
        level_gemm<<<grid, 256>>>(x_ids, mask, emb, s0, n);
        level_update<<<(n * HDIM + 255) / 256, 256>>>(s0, n, b_iou, b_f);
    }

    small_levels<<<1, 256>>>(x_ids, mask, emb, b_iou, b_f);

    out_gemm<<<(NNODES + 7) / 8, 256>>>(W_out, b_out, out);
}

// round 11
// speedup vs baseline: 1.2627x; 1.2627x over previous
#include <cuda_runtime.h>
#include <cuda_bf16.h>
#include <mma.h>
#include <cstdint>
#include <cstddef>

using namespace nvcuda;

#define DEPTH 18
#define NNODES ((1 << DEPTH) - 1)      // 262143
#define HDIM 128
#define LEAF_N (1 << (DEPTH - 1))      // 131072

// ================= device scratch (516 MiB total; largest object 192 MiB) =====
__device__ __align__(128) float g_h[(size_t)NNODES * HDIM];          // 128 MiB
__device__ __align__(128) float g_c[(size_t)NNODES * HDIM];          // 128 MiB
__device__ __align__(128) float g_fraw[(size_t)LEAF_N * HDIM];       // 64 MiB: raw fgate pre-act
__device__ __align__(128) float g_iouraw[(size_t)LEAF_N * 384];      // 192 MiB: raw iou pre-act
// weight images, bf16 pairs packed in uint32: [tile][n(128)][kpair(128)] (K=256)
// tiles 0-2: [W_iou;U_iou] n-tiles, tile 3: [W_f;U_f]
__device__ __align__(128) uint32_t g_Bhi[4 * 128 * 128];
__device__ __align__(128) uint32_t g_Blo[4 * 128 * 128];

__device__ __forceinline__ float sigmf(float x) { return 1.0f / (1.0f + __expf(-x)); }

// pure-integer bf16 hi/lo split (truncation): hi = top16(f), lo = top16(f - hi)
__device__ __forceinline__ void split2(float f0, float f1, uint32_t& hiw, uint32_t& low) {
    const uint32_t h0 = __float_as_uint(f0) & 0xFFFF0000u;
    const uint32_t h1 = __float_as_uint(f1) & 0xFFFF0000u;
    const uint32_t l0 = __float_as_uint(f0 - __uint_as_float(h0)) & 0xFFFF0000u;
    const uint32_t l1 = __float_as_uint(f1 - __uint_as_float(h1)) & 0xFFFF0000u;
    hiw = (h0 >> 16) | h1;
    low = (l0 >> 16) | l1;
}

// ================= static smem layout (bf16 elems, 40-elem padded rows) =====
#define PADK 40
#define E_ALO 5120
#define E_BHI 10240
#define E_BLO 15360
#define SM_ELEMS 20480            // 40 KB

// ================= one-time weight prep =================
__global__ void prep_weights(const float* __restrict__ Wiou, const float* __restrict__ Wf,
                             const float* __restrict__ Uiou, const float* __restrict__ Uf)
{
    const int idx = blockIdx.x * blockDim.x + threadIdx.x;
    if (idx >= 4 * 128 * 128) return;
    const int t = idx >> 14;
    const int n = (idx >> 7) & 127;
    const int kp = idx & 127;
    float v[2];
    #pragma unroll
    for (int e = 0; e < 2; e++) {
        const int k = kp * 2 + e;
        if (t < 3) {
            const int nn = t * 128 + n;
            v[e] = (k < 128) ? Wiou[k * 384 + nn] : Uiou[(k - 128) * 384 + nn];
        } else {
            v[e] = (k < 128) ? Wf[k * 128 + n] : Uf[(k - 128) * 128 + n];
        }
    }
    uint32_t hiw, low;
    split2(v[0], v[1], hiw, low);
    g_Bhi[idx] = hiw;
    g_Blo[idx] = low;
}

// ================= wmma GEMM core =================
// CTA = 128 rows x 128 cols, 8 warps (wm 0..3 = 32 rows, wn 0..1 = 64 cols).
// K chunked by 32; chunk kc<4 sources pe (emb row), kc>=4 sources ph0(+ph1 summed).
// bf16-split: acc += A_hi*B_hi + A_hi*B_lo + A_lo*B_hi (fragments register-cached).
__device__ __forceinline__ void gemm_core(
    __nv_bfloat16* sm, int tid,
    const float* pe, const float* ph0, const float* ph1,   // per-thread row ptrs (nullable)
    int nkc,
    const uint32_t* bhi, const uint32_t* blo,              // weight tile base (128n x 128kp)
    float* __restrict__ C, int ldC, int m0, int colbase)
{
    const int wid = tid >> 5;
    const int wm = wid >> 1;
    const int wn = wid & 1;
    const int r = tid >> 1;
    const int sel = tid & 1;

    wmma::fragment<wmma::accumulator, 16, 16, 16, float> acc[2][4];
    #pragma unroll
    for (int mt = 0; mt < 2; mt++)
        #pragma unroll
        for (int nt = 0; nt < 4; nt++)
            wmma::fill_fragment(acc[mt][nt], 0.0f);

    for (int kc = 0; kc < nkc; kc++) {
        if (kc) __syncthreads();
        // ---- stage A chunk (2 threads per row, 16 floats each) ----
        {
            const float* p0;
            const float* p1 = nullptr;
            if (kc < 4) {
                p0 = pe ? pe + kc * 32 + sel * 16 : nullptr;
            } else {
                p0 = ph0 ? ph0 + (kc - 4) * 32 + sel * 16 : nullptr;
                p1 = ph1 ? ph1 + (kc - 4) * 32 + sel * 16 : nullptr;
            }
            uint32_t* dhi = (uint32_t*)(sm + r * PADK) + sel * 8;
            uint32_t* dlo = (uint32_t*)(sm + E_ALO + r * PADK) + sel * 8;
            if (p0) {
                #pragma unroll
                for (int q = 0; q < 4; q++) {
                    float4 f = *(const float4*)(p0 + 4 * q);
                    if (p1) {
                        const float4 g = *(const float4*)(p1 + 4 * q);
                        f.x += g.x; f.y += g.y; f.z += g.z; f.w += g.w;
                    }
                    uint32_t h0, l0, h1, l1;
                    split2(f.x, f.y, h0, l0);
                    split2(f.z, f.w, h1, l1);
                    dhi[2 * q] = h0; dhi[2 * q + 1] = h1;
                    dlo[2 * q] = l0; dlo[2 * q + 1] = l1;
                }
            } else {
                #pragma unroll
                for (int q = 0; q < 8; q++) { dhi[q] = 0u; dlo[q] = 0u; }
            }
        }
        // ---- stage B chunk: 128 n-rows x 32 k (4 uint4/row; row = 32 uint4) ----
        {
            const uint4* shi = (const uint4*)bhi + kc * 4;
            const uint4* slo = (const uint4*)blo + kc * 4;
            #pragma unroll
            for (int i = tid; i < 512; i += 256) {
                const int nn = i >> 2;
                const int q = i & 3;
                *(uint4*)(sm + E_BHI + nn * PADK + q * 8) = shi[nn * 32 + q];
                *(uint4*)(sm + E_BLO + nn * PADK + q * 8) = slo[nn * 32 + q];
            }
        }
        __syncthreads();

        #pragma unroll
        for (int ks = 0; ks < 2; ks++) {
            wmma::fragment<wmma::matrix_a, 16, 16, 16, __nv_bfloat16, wmma::row_major> a_hi[2], a_lo[2];
            #pragma unroll
            for (int mt = 0; mt < 2; mt++) {
                const int arow = (wm * 32 + mt * 16) * PADK + ks * 16;
                wmma::load_matrix_sync(a_hi[mt], sm + arow, PADK);
                wmma::load_matrix_sync(a_lo[mt], sm + E_ALO + arow, PADK);
            }
            #pragma unroll
            for (int nt = 0; nt < 4; nt++) {
                const int brow = (wn * 64 + nt * 16) * PADK + ks * 16;
                wmma::fragment<wmma::matrix_b, 16, 16, 16, __nv_bfloat16, wmma::col_major> b_hi, b_lo;
                wmma::load_matrix_sync(b_hi, sm + E_BHI + brow, PADK);
                wmma::load_matrix_sync(b_lo, sm + E_BLO + brow, PADK);
                #pragma unroll
                for (int mt = 0; mt < 2; mt++) {
                    wmma::mma_sync(acc[mt][nt], a_hi[mt], b_hi, acc[mt][nt]);
                    wmma::mma_sync(acc[mt][nt], a_hi[mt], b_lo, acc[mt][nt]);
                    wmma::mma_sync(acc[mt][nt], a_lo[mt], b_hi, acc[mt][nt]);
                }
            }
        }
    }

    #pragma unroll
    for (int mt = 0; mt < 2; mt++)
        #pragma unroll
        for (int nt = 0; nt < 4; nt++) {
            const int row0 = m0 + wm * 32 + mt * 16;
            const int col0 = colbase + wn * 64 + nt * 16;
            wmma::store_matrix_sync(C + (size_t)row0 * ldC + col0, acc[mt][nt],
                                    ldC, wmma::mem_row_major);
        }
}

// leaves: g_iouraw[m] = emb(leaf m) @ W_iou (K=128); grid (3, 1024)
__global__ __launch_bounds__(256, 2)
void leaf_gemm(const int* __restrict__ xids, const int* __restrict__ msk,
               const float* __restrict__ emb)
{
    __shared__ __align__(16) __nv_bfloat16 sm[SM_ELEMS];
    const int tid = threadIdx.x;
    const int bt = blockIdx.x;
    const int m0 = blockIdx.y * 128;

    const int node = (LEAF_N - 1) + m0 + (tid >> 1);
    const int gid = xids[node] * msk[node];
    const float* pe = emb + (size_t)gid * HDIM;

    gemm_core(sm, tid, pe, nullptr, nullptr, 4,
              g_Bhi + bt * 16384, g_Blo + bt * 16384,
              g_iouraw, 384, m0, bt * 128);
}

// internal level: bx 0..2 = iou n-tiles (A=[emb(node)|h_l+h_r], K=256),
//                 bx 3    = fgate      (A=[emb(parent)|h_child], K=256)
__global__ __launch_bounds__(256, 2)
void level_gemm(const int* __restrict__ xids, const int* __restrict__ msk,
                const float* __restrict__ emb, int s0, int n)
{
    __shared__ __align__(16) __nv_bfloat16 sm[SM_ELEMS];
    const int tid = threadIdx.x;
    const int bx = blockIdx.x;
    const int m0 = blockIdx.y * 128;
    const int s1 = 2 * s0 + 1;
    const int r = tid >> 1;

    const float* pe = nullptr;
    const float* ph0 = nullptr;
    const float* ph1 = nullptr;

    if (bx < 3) {
        if (m0 >= n) return;
        const int m = m0 + r;
        if (m < n) {
            const int node = s0 + m;
            const int gid = xids[node] * msk[node];
            pe  = emb + (size_t)gid * HDIM;
            ph0 = g_h + (size_t)(s1 + 2 * m) * HDIM;
            ph1 = g_h + (size_t)(s1 + 2 * m + 1) * HDIM;
        }
        gemm_core(sm, tid, pe, ph0, ph1, 8,
                  g_Bhi + bx * 16384, g_Blo + bx * 16384,
                  g_iouraw, 384, m0, bx * 128);
    } else {
        const int ch = m0 + r;
        if (ch < 2 * n) {
            const int parent = s0 + (ch >> 1);
            const int gid = xids[parent] * msk[parent];
            pe  = emb + (size_t)gid * HDIM;
            ph0 = g_h + (size_t)(s1 + ch) * HDIM;
        }
        gemm_core(sm, tid, pe, ph0, nullptr, 8,
                  g_Bhi + 3 * 16384, g_Blo + 3 * 16384,
                  g_fraw, 128, m0, 0);
    }
}

// ================= elementwise (biases folded here) =================
__global__ void leaf_update(const float* __restrict__ biou)
{
    const int idx = blockIdx.x * blockDim.x + threadIdx.x;
    if (idx >= LEAF_N * HDIM) return;
    const int m = idx >> 7;
    const int j = idx & 127;
    const int node = (LEAF_N - 1) + m;
    const float iv = g_iouraw[(size_t)m * 384 + j]       + biou[j];
    const float ov = g_iouraw[(size_t)m * 384 + 128 + j] + biou[128 + j];
    const float uv = g_iouraw[(size_t)m * 384 + 256 + j] + biou[256 + j];
    const float cv = sigmf(iv) * tanhf(uv);
    const float hv = sigmf(ov) * tanhf(cv);
    g_c[(size_t)node * HDIM + j] = cv;
    g_h[(size_t)node * HDIM + j] = hv;
}

__global__ void level_update(int s0, int n,
                             const float* __restrict__ biou, const float* __restrict__ bfv)
{
    const int idx = blockIdx.x * blockDim.x + threadIdx.x;
    if (idx >= n * HDIM) return;
    const int m = idx >> 7;
    const int j = idx & 127;
    const int node = s0 + m;
    const float bf = bfv[j];
    const float c0 = g_c[(size_t)(2 * node + 1) * HDIM + j];
    const float c1 = g_c[(size_t)(2 * node + 2) * HDIM + j];
    const float f0 = sigmf(g_fraw[(size_t)(2 * m) * HDIM + j] + bf);
    const float f1 = sigmf(g_fraw[(size_t)(2 * m + 1) * HDIM + j] + bf);
    const float fc = f0 * c0 + f1 * c1;
    const float iv = g_iouraw[(size_t)m * 384 + j]       + biou[j];
    const float ov = g_iouraw[(size_t)m * 384 + 128 + j] + biou[128 + j];
    const float uv = g_iouraw[(size_t)m * 384 + 256 + j] + biou[256 + j];
    const float cv = sigmf(iv) * tanhf(uv) + fc;
    const float hv = sigmf(ov) * tanhf(cv);
    g_c[(size_t)node * HDIM + j] = cv;
    g_h[(size_t)node * HDIM + j] = hv;
}

// ================= output projection =================
__global__ void out_gemm(const float* __restrict__ Wout,
                         const float* __restrict__ bout,
                         float* __restrict__ out)
{
    __shared__ float Ws[HDIM * 5];
    __shared__ float bs[5];
    const int tid = threadIdx.x;
    for (int i = tid; i < HDIM * 5; i += blockDim.x) Ws[i] = Wout[i];
    if (tid < 5) bs[tid] = bout[tid];
    __syncthreads();

    const int node = (blockIdx.x * blockDim.x + tid) >> 5;
    const int lane = tid & 31;
    if (node >= NNODES) return;

    const float* hp = g_h + (size_t)node * HDIM;
    float p[5] = {0.f, 0.f, 0.f, 0.f, 0.f};
    #pragma unroll
    for (int e = 0; e < 4; e++) {
        const int k = e * 32 + lane;
        const float x = hp[k];
        #pragma unroll
        for (int c = 0; c < 5; c++) p[c] += x * Ws[k * 5 + c];
    }
    #pragma unroll
    for (int off = 16; off > 0; off >>= 1)
        #pragma unroll
        for (int c = 0; c < 5; c++)
            p[c] += __shfl_xor_sync(0xffffffffu, p[c], off);

    if (lane == 0) {
        #pragma unroll
        for (int c = 0; c < 5; c++)
            out[(size_t)node * 5 + c] = p[c] + bs[c];
    }
}

// ================= launch =================
extern "C" void kernel_launch(void* const* d_in, const int* in_sizes, int n_in,
                              void* d_out, int out_size)
{
    const int*   x_ids = (const int*)d_in[0];
    const int*   mask  = (const int*)d_in[1];
    const float* emb   = (const float*)d_in[2];
    const float* W_iou = (const float*)d_in[3];
    const float* U_iou = (const float*)d_in[4];
    const float* b_iou = (const float*)d_in[5];
    const float* W_f   = (const float*)d_in[6];
    const float* U_f   = (const float*)d_in[7];
    const float* b_f   = (const float*)d_in[8];
    const float* W_out = (const float*)d_in[9];
    const float* b_out = (const float*)d_in[10];
    float* out = (float*)d_out;

    prep_weights<<<(4 * 128 * 128 + 255) / 256, 256>>>(W_iou, W_f, U_iou, U_f);

    {
        dim3 grid(3, LEAF_N / 128);
        leaf_gemm<<<grid, 256>>>(x_ids, mask, emb);
        leaf_update<<<(LEAF_N * HDIM + 255) / 256, 256>>>(b_iou);
    }

    for (int d = DEPTH - 2; d >= 0; --d) {
        const int n = 1 << d;
        const int s0 = n - 1;
        dim3 grid(4, (2 * n + 127) / 128);
        level_gemm<<<grid, 256>>>(x_ids, mask, emb, s0, n);
        level_update<<<(n * HDIM + 255) / 256, 256>>>(s0, n, b_iou, b_f);
    }

    out_gemm<<<(NNODES + 7) / 8, 256>>>(W_out, b_out, out);
}

// round 12
// speedup vs baseline: 1.2962x; 1.0265x over previous
#include <cuda_runtime.h>
#include <cuda_bf16.h>
#include <mma.h>
#include <cstdint>
#include <cstddef>

using namespace nvcuda;

#define DEPTH 18
#define NNODES ((1 << DEPTH) - 1)      // 262143
#define HDIM 128
#define LEAF_N (1 << (DEPTH - 1))      // 131072

// ================= device scratch (516 MiB total; largest object 192 MiB) =====
__device__ __align__(128) float g_h[(size_t)NNODES * HDIM];          // 128 MiB
__device__ __align__(128) float g_c[(size_t)NNODES * HDIM];          // 128 MiB
__device__ __align__(128) float g_fraw[(size_t)LEAF_N * HDIM];       // 64 MiB: raw fgate pre-act
__device__ __align__(128) float g_iouraw[(size_t)LEAF_N * 384];      // 192 MiB: raw iou pre-act
// weight images, bf16 pairs packed in uint32: [tile][n(128)][kpair(128)] (K=256)
// tiles 0-2: [W_iou;U_iou] n-tiles, tile 3: [W_f;U_f]
__device__ __align__(128) uint32_t g_Bhi[4 * 128 * 128];
__device__ __align__(128) uint32_t g_Blo[4 * 128 * 128];

__device__ __forceinline__ float sigmf(float x) { return 1.0f / (1.0f + __expf(-x)); }

// pure-integer bf16 hi/lo split (truncation): hi = top16(f), lo = top16(f - hi)
__device__ __forceinline__ void split2(float f0, float f1, uint32_t& hiw, uint32_t& low) {
    const uint32_t h0 = __float_as_uint(f0) & 0xFFFF0000u;
    const uint32_t h1 = __float_as_uint(f1) & 0xFFFF0000u;
    const uint32_t l0 = __float_as_uint(f0 - __uint_as_float(h0)) & 0xFFFF0000u;
    const uint32_t l1 = __float_as_uint(f1 - __uint_as_float(h1)) & 0xFFFF0000u;
    hiw = (h0 >> 16) | h1;
    low = (l0 >> 16) | l1;
}

// ================= static smem layout (bf16 elems, 40-elem padded rows) =====
#define PADK 40
#define E_ALO 5120
#define E_BHI 10240
#define E_BLO 15360
#define SM_ELEMS 20480            // 40 KB

// ================= one-time weight prep =================
__global__ void prep_weights(const float* __restrict__ Wiou, const float* __restrict__ Wf,
                             const float* __restrict__ Uiou, const float* __restrict__ Uf)
{
    const int idx = blockIdx.x * blockDim.x + threadIdx.x;
    if (idx >= 4 * 128 * 128) return;
    const int t = idx >> 14;
    const int n = (idx >> 7) & 127;
    const int kp = idx & 127;
    float v[2];
    #pragma unroll
    for (int e = 0; e < 2; e++) {
        const int k = kp * 2 + e;
        if (t < 3) {
            const int nn = t * 128 + n;
            v[e] = (k < 128) ? Wiou[k * 384 + nn] : Uiou[(k - 128) * 384 + nn];
        } else {
            v[e] = (k < 128) ? Wf[k * 128 + n] : Uf[(k - 128) * 128 + n];
        }
    }
    uint32_t hiw, low;
    split2(v[0], v[1], hiw, low);
    g_Bhi[idx] = hiw;
    g_Blo[idx] = low;
}

// ================= wmma GEMM core (register-prefetch pipelined) ============
// CTA = 128 rows x 128 cols, 8 warps (wm 0..3 = 32 rows, wn 0..1 = 64 cols).
// K chunked by 32; chunk kc<4 sources pe (emb row), kc>=4 sources ph0(+ph1 summed).
// bf16-split: acc += A_hi*B_hi + A_hi*B_lo + A_lo*B_hi (fragments register-cached).
// Pipeline: gmem loads for chunk kc are ISSUED before the barrier that waits on
// compute(kc-1); first use (split/STS) comes after it, so LDG latency overlaps
// the barrier wait and the co-resident CTA's compute.
__device__ __forceinline__ void gemm_core(
    __nv_bfloat16* sm, int tid,
    const float* pe, const float* ph0, const float* ph1,   // per-thread row ptrs (nullable)
    int nkc,
    const uint32_t* bhi, const uint32_t* blo,              // weight tile base (128n x 128kp)
    float* __restrict__ C, int ldC, int m0, int colbase)
{
    const int wid = tid >> 5;
    const int wm = wid >> 1;
    const int wn = wid & 1;
    const int r = tid >> 1;
    const int sel = tid & 1;

    // B prefetch addressing (2 rows per thread per plane)
    const int bnn0 = tid >> 2;
    const int bq   = tid & 3;

    wmma::fragment<wmma::accumulator, 16, 16, 16, float> acc[2][4];
    #pragma unroll
    for (int mt = 0; mt < 2; mt++)
        #pragma unroll
        for (int nt = 0; nt < 4; nt++)
            wmma::fill_fragment(acc[mt][nt], 0.0f);

    for (int kc = 0; kc < nkc; kc++) {
        // ---- issue gmem loads for this chunk (no use before the barrier) ----
        float a0[16], a1[16];
        bool haveP1;
        {
            const float* p0;
            const float* p1 = nullptr;
            if (kc < 4) {
                p0 = pe ? pe + kc * 32 + sel * 16 : nullptr;
            } else {
                p0 = ph0 ? ph0 + (kc - 4) * 32 + sel * 16 : nullptr;
                p1 = ph1 ? ph1 + (kc - 4) * 32 + sel * 16 : nullptr;
            }
            haveP1 = (p1 != nullptr);
            if (p0) {
                #pragma unroll
                for (int q = 0; q < 4; q++)
                    *(float4*)(a0 + 4 * q) = *(const float4*)(p0 + 4 * q);
            } else {
                #pragma unroll
                for (int e = 0; e < 16; e++) a0[e] = 0.f;
            }
            if (p1) {
                #pragma unroll
                for (int q = 0; q < 4; q++)
                    *(float4*)(a1 + 4 * q) = *(const float4*)(p1 + 4 * q);
            }
        }
        const uint4* shi = (const uint4*)bhi + kc * 4;
        const uint4* slo = (const uint4*)blo + kc * 4;
        uint4 pbh0 = shi[bnn0 * 32 + bq];
        uint4 pbh1 = shi[(bnn0 + 64) * 32 + bq];
        uint4 pbl0 = slo[bnn0 * 32 + bq];
        uint4 pbl1 = slo[(bnn0 + 64) * 32 + bq];

        if (kc) __syncthreads();   // wait compute(kc-1); loads above stay in flight

        // ---- consume: split + STS ----
        {
            uint32_t* dhi = (uint32_t*)(sm + r * PADK) + sel * 8;
            uint32_t* dlo = (uint32_t*)(sm + E_ALO + r * PADK) + sel * 8;
            #pragma unroll
            for (int q = 0; q < 4; q++) {
                float fx = a0[4 * q], fy = a0[4 * q + 1], fz = a0[4 * q + 2], fw = a0[4 * q + 3];
                if (haveP1) {
                    fx += a1[4 * q]; fy += a1[4 * q + 1]; fz += a1[4 * q + 2]; fw += a1[4 * q + 3];
                }
                uint32_t h0, l0, h1, l1;
                split2(fx, fy, h0, l0);
                split2(fz, fw, h1, l1);
                dhi[2 * q] = h0; dhi[2 * q + 1] = h1;
                dlo[2 * q] = l0; dlo[2 * q + 1] = l1;
            }
            *(uint4*)(sm + E_BHI + bnn0 * PADK + bq * 8) = pbh0;
            *(uint4*)(sm + E_BHI + (bnn0 + 64) * PADK + bq * 8) = pbh1;
            *(uint4*)(sm + E_BLO + bnn0 * PADK + bq * 8) = pbl0;
            *(uint4*)(sm + E_BLO + (bnn0 + 64) * PADK + bq * 8) = pbl1;
        }
        __syncthreads();

        // ---- compute ----
        #pragma unroll
        for (int ks = 0; ks < 2; ks++) {
            wmma::fragment<wmma::matrix_a, 16, 16, 16, __nv_bfloat16, wmma::row_major> a_hi[2], a_lo[2];
            #pragma unroll
            for (int mt = 0; mt < 2; mt++) {
                const int arow = (wm * 32 + mt * 16) * PADK + ks * 16;
                wmma::load_matrix_sync(a_hi[mt], sm + arow, PADK);
                wmma::load_matrix_sync(a_lo[mt], sm + E_ALO + arow, PADK);
            }
            #pragma unroll
            for (int nt = 0; nt < 4; nt++) {
                const int brow = (wn * 64 + nt * 16) * PADK + ks * 16;
                wmma::fragment<wmma::matrix_b, 16, 16, 16, __nv_bfloat16, wmma::col_major> b_hi, b_lo;
                wmma::load_matrix_sync(b_hi, sm + E_BHI + brow, PADK);
                wmma::load_matrix_sync(b_lo, sm + E_BLO + brow, PADK);
                #pragma unroll
                for (int mt = 0; mt < 2; mt++) {
                    wmma::mma_sync(acc[mt][nt], a_hi[mt], b_hi, acc[mt][nt]);
                    wmma::mma_sync(acc[mt][nt], a_hi[mt], b_lo, acc[mt][nt]);
                    wmma::mma_sync(acc[mt][nt], a_lo[mt], b_hi, acc[mt][nt]);
                }
            }
        }
    }

    #pragma unroll
    for (int mt = 0; mt < 2; mt++)
        #pragma unroll
        for (int nt = 0; nt < 4; nt++) {
            const int row0 = m0 + wm * 32 + mt * 16;
            const int col0 = colbase + wn * 64 + nt * 16;
            wmma::store_matrix_sync(C + (size_t)row0 * ldC + col0, acc[mt][nt],
                                    ldC, wmma::mem_row_major);
        }
}

// leaves: g_iouraw[m] = emb(leaf m) @ W_iou (K=128); grid (3, 1024)
__global__ __launch_bounds__(256, 2)
void leaf_gemm(const int* __restrict__ xids, const int* __restrict__ msk,
               const float* __restrict__ emb)
{
    __shared__ __align__(16) __nv_bfloat16 sm[SM_ELEMS];
    const int tid = threadIdx.x;
    const int bt = blockIdx.x;
    const int m0 = blockIdx.y * 128;

    const int node = (LEAF_N - 1) + m0 + (tid >> 1);
    const int gid = xids[node] * msk[node];
    const float* pe = emb + (size_t)gid * HDIM;

    gemm_core(sm, tid, pe, nullptr, nullptr, 4,
              g_Bhi + bt * 16384, g_Blo + bt * 16384,
              g_iouraw, 384, m0, bt * 128);
}

// internal level: bx 0..2 = iou n-tiles (A=[emb(node)|h_l+h_r], K=256),
//                 bx 3    = fgate      (A=[emb(parent)|h_child], K=256)
__global__ __launch_bounds__(256, 2)
void level_gemm(const int* __restrict__ xids, const int* __restrict__ msk,
                const float* __restrict__ emb, int s0, int n)
{
    __shared__ __align__(16) __nv_bfloat16 sm[SM_ELEMS];
    const int tid = threadIdx.x;
    const int bx = blockIdx.x;
    const int m0 = blockIdx.y * 128;
    const int s1 = 2 * s0 + 1;
    const int r = tid >> 1;

    const float* pe = nullptr;
    const float* ph0 = nullptr;
    const float* ph1 = nullptr;

    if (bx < 3) {
        if (m0 >= n) return;
        const int m = m0 + r;
        if (m < n) {
            const int node = s0 + m;
            const int gid = xids[node] * msk[node];
            pe  = emb + (size_t)gid * HDIM;
            ph0 = g_h + (size_t)(s1 + 2 * m) * HDIM;
            ph1 = g_h + (size_t)(s1 + 2 * m + 1) * HDIM;
        }
        gemm_core(sm, tid, pe, ph0, ph1, 8,
                  g_Bhi + bx * 16384, g_Blo + bx * 16384,
                  g_iouraw, 384, m0, bx * 128);
    } else {
        const int ch = m0 + r;
        if (ch < 2 * n) {
            const int parent = s0 + (ch >> 1);
            const int gid = xids[parent] * msk[parent];
            pe  = emb + (size_t)gid * HDIM;
            ph0 = g_h + (size_t)(s1 + ch) * HDIM;
        }
        gemm_core(sm, tid, pe, ph0, nullptr, 8,
                  g_Bhi + 3 * 16384, g_Blo + 3 * 16384,
                  g_fraw, 128, m0, 0);
    }
}

// ================= elementwise (biases folded here) =================
__global__ void leaf_update(const float* __restrict__ biou)
{
    const int idx = blockIdx.x * blockDim.x + threadIdx.x;
    if (idx >= LEAF_N * HDIM) return;
    const int m = idx >> 7;
    const int j = idx & 127;
    const int node = (LEAF_N - 1) + m;
    const float iv = g_iouraw[(size_t)m * 384 + j]       + biou[j];
    const float ov = g_iouraw[(size_t)m * 384 + 128 + j] + biou[128 + j];
    const float uv = g_iouraw[(size_t)m * 384 + 256 + j] + biou[256 + j];
    const float cv = sigmf(iv) * tanhf(uv);
    const float hv = sigmf(ov) * tanhf(cv);
    g_c[(size_t)node * HDIM + j] = cv;
    g_h[(size_t)node * HDIM + j] = hv;
}

__global__ void level_update(int s0, int n,
                             const float* __restrict__ biou, const float* __restrict__ bfv)
{
    const int idx = blockIdx.x * blockDim.x + threadIdx.x;
    if (idx >= n * HDIM) return;
    const int m = idx >> 7;
    const int j = idx & 127;
    const int node = s0 + m;
    const float bf = bfv[j];
    const float c0 = g_c[(size_t)(2 * node + 1) * HDIM + j];
    const float c1 = g_c[(size_t)(2 * node + 2) * HDIM + j];
    const float f0 = sigmf(g_fraw[(size_t)(2 * m) * HDIM + j] + bf);
    const float f1 = sigmf(g_fraw[(size_t)(2 * m + 1) * HDIM + j] + bf);
    const float fc = f0 * c0 + f1 * c1;
    const float iv = g_iouraw[(size_t)m * 384 + j]       + biou[j];
    const float ov = g_iouraw[(size_t)m * 384 + 128 + j] + biou[128 + j];
    const float uv = g_iouraw[(size_t)m * 384 + 256 + j] + biou[256 + j];
    const float cv = sigmf(iv) * tanhf(uv) + fc;
    const float hv = sigmf(ov) * tanhf(cv);
    g_c[(size_t)node * HDIM + j] = cv;
    g_h[(size_t)node * HDIM + j] = hv;
}

// ================= output projection =================
__global__ void out_gemm(const float* __restrict__ Wout,
                         const float* __restrict__ bout,
                         float* __restrict__ out)
{
    __shared__ float Ws[HDIM * 5];
    __shared__ float bs[5];
    const int tid = threadIdx.x;
    for (int i = tid; i < HDIM * 5; i += blockDim.x) Ws[i] = Wout[i];
    if (tid < 5) bs[tid] = bout[tid];
    __syncthreads();

    const int node = (blockIdx.x * blockDim.x + tid) >> 5;
    const int lane = tid & 31;
    if (node >= NNODES) return;

    const float* hp = g_h + (size_t)node * HDIM;
    float p[5] = {0.f, 0.f, 0.f, 0.f, 0.f};
    #pragma unroll
    for (int e = 0; e < 4; e++) {
        const int k = e * 32 + lane;
        const float x = hp[k];
        #pragma unroll
        for (int c = 0; c < 5; c++) p[c] += x * Ws[k * 5 + c];
    }
    #pragma unroll
    for (int off = 16; off > 0; off >>= 1)
        #pragma unroll
        for (int c = 0; c < 5; c++)
            p[c] += __shfl_xor_sync(0xffffffffu, p[c], off);

    if (lane == 0) {
        #pragma unroll
        for (int c = 0; c < 5; c++)
            out[(size_t)node * 5 + c] = p[c] + bs[c];
    }
}

// ================= launch =================
extern "C" void kernel_launch(void* const* d_in, const int* in_sizes, int n_in,
                              void* d_out, int out_size)
{
    const int*   x_ids = (const int*)d_in[0];
    const int*   mask  = (const int*)d_in[1];
    const float* emb   = (const float*)d_in[2];
    const float* W_iou = (const float*)d_in[3];
    const float* U_iou = (const float*)d_in[4];
    const float* b_iou = (const float*)d_in[5];
    const float* W_f   = (const float*)d_in[6];
    const float* U_f   = (const float*)d_in[7];
    const float* b_f   = (const float*)d_in[8];
    const float* W_out = (const float*)d_in[9];
    const float* b_out = (const float*)d_in[10];
    float* out = (float*)d_out;

    prep_weights<<<(4 * 128 * 128 + 255) / 256, 256>>>(W_iou, W_f, U_iou, U_f);

    {
        dim3 grid(3, LEAF_N / 128);
        leaf_gemm<<<grid, 256>>>(x_ids, mask, emb);
        leaf_update<<<(LEAF_N * HDIM + 255) / 256, 256>>>(b_iou);
    }

    for (int d = DEPTH - 2; d >= 0; --d) {
        const int n = 1 << d;
        const int s0 = n - 1;
        dim3 grid(4, (2 * n + 127) / 128);
        level_gemm<<<grid, 256>>>(x_ids, mask, emb, s0, n);
        level_update<<<(n * HDIM + 255) / 256, 256>>>(s0, n, b_iou, b_f);
    }

    out_gemm<<<(NNODES + 7) / 8, 256>>>(W_out, b_out, out);
}